// round 2
// baseline (speedup 1.0000x reference)
#include <cuda_runtime.h>

#define NBOX 16384
#define NW   256            // 64-bit words per mask row
#define CONF_THRESH 0.5f
#define PIOU_THRESH 0.5f

// ---------------- device scratch (static; no allocation) ----------------
__device__ float4 g_seph[NBOX];                    // sorted [start,end,peak,height]
__device__ float  g_conf[NBOX];                    // dense confidence (unsorted)
__device__ int    g_rank[NBOX];                    // sorted position of original idx
__device__ int    g_M;                             // count(conf > 0.5) == valid prefix len
__device__ unsigned long long g_mask[(size_t)NBOX * NW];   // 32MB suppression bitmask
__device__ unsigned long long g_keep[NW];          // final keep bits (sorted order)

// ---------------- 1) gather conf, zero accumulators ----------------
__global__ void k_prep(const float* __restrict__ in) {
    int i = blockIdx.x * blockDim.x + threadIdx.x;
    if (i < NBOX) {
        g_conf[i] = in[i * 5 + 0];
        g_rank[i] = 0;
    }
    if (i == 0) g_M = 0;
}

// ---------------- 2) stable descending rank via O(N^2) counting ----------------
// grid = (64, 4), block = 256. Each thread owns one i, counts one quarter of j.
__global__ void k_rank() {
    __shared__ float tile[256];
    int i  = blockIdx.x * 256 + threadIdx.x;
    float ci = g_conf[i];
    int base = blockIdx.y * 4096;
    int cnt = 0;
    for (int jt = 0; jt < 4096; jt += 256) {
        tile[threadIdx.x] = g_conf[base + jt + threadIdx.x];
        __syncthreads();
#pragma unroll 8
        for (int k = 0; k < 256; k++) {
            float c = tile[k];
            int   j = base + jt + k;
            cnt += (c > ci) || (c == ci && j < i);   // stable: ties by original index
        }
        __syncthreads();
    }
    atomicAdd(&g_rank[i], cnt);
}

// ---------------- 3) scatter boxes into sorted order; count valid ----------------
__global__ void k_scatter(const float* __restrict__ in) {
    int i = blockIdx.x * blockDim.x + threadIdx.x;
    if (i >= NBOX) return;
    int r = g_rank[i];
    const float* row = in + (size_t)i * 5;
    g_seph[r] = make_float4(row[1], row[2], row[3], row[4]);
    if (row[0] > CONF_THRESH) atomicAdd(&g_M, 1);
}

// ---------------- 4) pairwise peak-IoU suppression bitmask ----------------
// grid = (256 colblocks, 256 rowblocks), block = 64. Row r vs 64 columns -> one word.
// Fast path skips non-overlapping pairs exactly (iou=0 => piou<=0 < 0.5).
// Slow path uses round-to-nearest intrinsics (no FMA contraction) to match XLA fp32.
__global__ void k_mask() {
    __shared__ float4 cols[64];
    int M = g_M;
    if ((int)(blockIdx.y * 64) >= M) return;          // rows never read
    int r  = blockIdx.y * 64 + threadIdx.x;
    int j0 = blockIdx.x * 64;
    cols[threadIdx.x] = g_seph[j0 + threadIdx.x];
    __syncthreads();
    if (r >= M) return;
    float4 a = g_seph[r];
    float area1 = __fmul_rn(__fsub_rn(a.y, a.x), a.w);
    unsigned long long w = 0;
#pragma unroll 4
    for (int k = 0; k < 64; k++) {
        int j = j0 + k;
        float4 b = cols[k];
        float is = fmaxf(a.x, b.x);
        float ie = fminf(a.y, b.y);
        float il = __fsub_rn(ie, is);
        bool sup = false;
        if (il > 0.0f && j < M && j != r) {
            float inter_len  = il;                       // == clip(ie-is, 0) when > 0
            float inter_h    = fminf(a.w, b.w);
            float inter_area = __fmul_rn(inter_len, inter_h);
            float area2      = __fmul_rn(__fsub_rn(b.y, b.x), b.w);
            float union_area = __fsub_rn(__fadd_rn(area1, area2), inter_area);
            float iou        = __fdiv_rn(inter_area, union_area);
            float pd         = fabsf(__fsub_rn(a.z, b.z));
            float us         = fminf(a.x, b.x);
            float ue         = fmaxf(a.y, b.y);
            float ud         = fabsf(__fsub_rn(ue, us));
            float val        = __fsub_rn(iou, __fdiv_rn(pd, ud));
            sup = (val > PIOU_THRESH);
        }
        w |= ((unsigned long long)sup) << k;
    }
    g_mask[(size_t)r * NW + blockIdx.x] = w;
}

// ---------------- 5) greedy scan, chunked 64-at-a-time ----------------
// Single CTA, 256 threads. Per chunk: thread 0 runs the 64-step dependent chain
// in registers (diag words), then all 256 threads OR kept rows into shared remv
// with fully independent loads.
__global__ void k_scan() {
    __shared__ unsigned long long remv[NW];
    __shared__ unsigned long long diag[64];
    __shared__ unsigned long long kept_sh;
    int t = threadIdx.x;
    remv[t] = 0ULL;
    int M = g_M;
    for (int c = 0; c < NW; c++) {
        if (t < 64) {
            int r = c * 64 + t;
            diag[t] = (r < M) ? g_mask[(size_t)r * NW + c] : 0ULL;
        }
        __syncthreads();                       // diag ready + prev-iter remv writes visible
        if (t == 0) {
            unsigned long long rm = remv[c];
            unsigned long long kept = 0ULL;
            int lim = M - c * 64;
            if (lim > 64) lim = 64;
            for (int b = 0; b < lim; b++) {
                if (!((rm >> b) & 1ULL)) {
                    kept |= 1ULL << b;
                    rm   |= diag[b];           // intra-chunk suppression
                }
            }
            kept_sh   = kept;
            g_keep[c] = kept;
        }
        __syncthreads();                       // kept_sh published
        unsigned long long kw  = kept_sh;
        unsigned long long acc = remv[t];
        while (kw) {
            int b = __ffsll((long long)kw) - 1;
            kw &= kw - 1ULL;
            acc |= g_mask[(size_t)(c * 64 + b) * NW + t];   // independent loads (MLP)
        }
        remv[t] = acc;
    }
}

// ---------------- 6) write output: sorted boxes[:,1:5] * keep ----------------
__global__ void k_out(float4* __restrict__ out) {
    int i = blockIdx.x * blockDim.x + threadIdx.x;
    if (i >= NBOX) return;
    unsigned long long kw = g_keep[i >> 6];
    float4 v = ((kw >> (i & 63)) & 1ULL) ? g_seph[i] : make_float4(0.f, 0.f, 0.f, 0.f);
    out[i] = v;
}

extern "C" void kernel_launch(void* const* d_in, const int* in_sizes, int n_in,
                              void* d_out, int out_size) {
    const float* in = (const float*)d_in[0];
    float4* out = (float4*)d_out;
    (void)in_sizes; (void)n_in; (void)out_size;

    k_prep   <<<64, 256>>>(in);
    k_rank   <<<dim3(64, 4), 256>>>();
    k_scatter<<<64, 256>>>(in);
    k_mask   <<<dim3(256, 256), 64>>>();
    k_scan   <<<1, 256>>>();
    k_out    <<<64, 256>>>(out);
}

// round 3
// speedup vs baseline: 1.7231x; 1.7231x over previous
#include <cuda_runtime.h>

#define NBOX 16384
#define NW   256            // 64-bit words per mask row
#define CONF_THRESH 0.5f
#define PIOU_THRESH 0.5f

typedef unsigned long long u64;

// ---------------- device scratch (static; no allocation) ----------------
__device__ float4 g_seph[NBOX];                    // sorted [start,end,peak,height]
__device__ float  g_conf[NBOX];                    // dense confidence (unsorted)
__device__ int    g_rank[NBOX];                    // sorted position of original idx
__device__ int    g_M;                             // count(conf > 0.5) == valid prefix len
__device__ u64    g_mask[(size_t)NBOX * NW];       // 32MB suppression bitmask
__device__ u64    g_keep[NW];                      // final keep bits (sorted order)

// ---------------- 1) gather conf, zero accumulators ----------------
__global__ void k_prep(const float* __restrict__ in) {
    int i = blockIdx.x * blockDim.x + threadIdx.x;
    if (i < NBOX) {
        g_conf[i] = in[i * 5 + 0];
        g_rank[i] = 0;
    }
    if (i == 0) g_M = 0;
}

// ---------------- 2) stable descending rank via O(N^2) counting ----------------
__global__ void k_rank() {
    __shared__ float tile[256];
    int i  = blockIdx.x * 256 + threadIdx.x;
    float ci = g_conf[i];
    int base = blockIdx.y * 4096;
    int cnt = 0;
    for (int jt = 0; jt < 4096; jt += 256) {
        tile[threadIdx.x] = g_conf[base + jt + threadIdx.x];
        __syncthreads();
#pragma unroll 8
        for (int k = 0; k < 256; k++) {
            float c = tile[k];
            int   j = base + jt + k;
            cnt += (c > ci) || (c == ci && j < i);   // stable: ties by original index
        }
        __syncthreads();
    }
    atomicAdd(&g_rank[i], cnt);
}

// ---------------- 3) scatter boxes into sorted order; count valid ----------------
__global__ void k_scatter(const float* __restrict__ in) {
    int i = blockIdx.x * blockDim.x + threadIdx.x;
    if (i >= NBOX) return;
    int r = g_rank[i];
    const float* row = in + (size_t)i * 5;
    g_seph[r] = make_float4(row[1], row[2], row[3], row[4]);
    if (row[0] > CONF_THRESH) atomicAdd(&g_M, 1);
}

// ---------------- 4) pairwise peak-IoU suppression bitmask (valid M x M only) ----
// grid = (256, 256) col/row 64-blocks, block = 64. Early-exit outside [0,M)^2.
// Round-to-nearest intrinsics (no FMA contraction) to match XLA fp32 exactly.
__global__ void k_mask() {
    __shared__ float4 cols[64];
    int M = g_M;
    if ((int)(blockIdx.y * 64) >= M) return;          // rows never read
    if ((int)(blockIdx.x * 64) >= M) return;          // cols never read by scan
    int r  = blockIdx.y * 64 + threadIdx.x;
    int j0 = blockIdx.x * 64;
    cols[threadIdx.x] = g_seph[j0 + threadIdx.x];
    __syncthreads();
    if (r >= M) return;
    float4 a = g_seph[r];
    float area1 = __fmul_rn(__fsub_rn(a.y, a.x), a.w);
    u64 w = 0;
#pragma unroll 4
    for (int k = 0; k < 64; k++) {
        int j = j0 + k;
        float4 b = cols[k];
        float is = fmaxf(a.x, b.x);
        float ie = fminf(a.y, b.y);
        float il = __fsub_rn(ie, is);
        bool sup = false;
        if (il > 0.0f && j < M && j != r) {           // piou>0 requires overlap
            float inter_h    = fminf(a.w, b.w);
            float inter_area = __fmul_rn(il, inter_h);
            float area2      = __fmul_rn(__fsub_rn(b.y, b.x), b.w);
            float union_area = __fsub_rn(__fadd_rn(area1, area2), inter_area);
            float iou        = __fdiv_rn(inter_area, union_area);
            float pd         = fabsf(__fsub_rn(a.z, b.z));
            float us         = fminf(a.x, b.x);
            float ue         = fmaxf(a.y, b.y);
            float ud         = fabsf(__fsub_rn(ue, us));
            float val        = __fsub_rn(iou, __fdiv_rn(pd, ud));
            sup = (val > PIOU_THRESH);
        }
        w |= ((u64)sup) << k;
    }
    g_mask[(size_t)r * NW + blockIdx.x] = w;
}

// ---------------- 5) greedy scan, chunked 64-at-a-time, register chain ----------
// Single CTA, 256 threads, Mw chunks. Per chunk:
//   (A) threads 64..127 prefetch next chunk's diag (double buffered)
//   (B) thread 0: copy diag to regs, run 64-step branchless chain, emit kept list
//   S1; (C) threads t in (c, Mw) OR kept rows' mask words into remv; S2.
__global__ void __launch_bounds__(256, 1) k_scan() {
    __shared__ u64 remv[NW];
    __shared__ u64 diag[2][64];
    __shared__ u64 kept_sh;
    __shared__ int klist[64];
    __shared__ int kcnt_sh;
    int t = threadIdx.x;
    remv[t] = 0ULL;
    int M  = g_M;
    int Mw = (M + 63) >> 6;
    if (t >= Mw) g_keep[t] = 0ULL;                 // zero unused keep words
    if (t < 64) {                                  // load chunk 0 diag
        diag[0][t] = (t < M) ? g_mask[(size_t)t * NW + 0] : 0ULL;
    }
    __syncthreads();

    for (int c = 0; c < Mw; c++) {
        int buf = c & 1;
        // (A) prefetch next chunk's diagonal block
        if (t >= 64 && t < 128 && (c + 1) < Mw) {
            int r = (c + 1) * 64 + (t - 64);
            diag[buf ^ 1][t - 64] = (r < M) ? g_mask[(size_t)r * NW + (c + 1)] : 0ULL;
        }
        // (B) serial chain in registers
        if (t == 0) {
            u64 d[64];
#pragma unroll
            for (int b = 0; b < 64; b++) d[b] = diag[buf][b];
            u64 rm   = remv[c];
            u64 kept = 0ULL;
#pragma unroll
            for (int b = 0; b < 64; b++) {
                u64 m = ((rm >> b) & 1ULL) - 1ULL;   // ~0 keep, 0 removed
                kept |= (1ULL << b) & m;
                rm   |= d[b] & m;
            }
            int lim = M - (c << 6);
            u64 vmask = (lim >= 64) ? ~0ULL : ((1ULL << lim) - 1ULL);
            kept &= vmask;
            kept_sh   = kept;
            g_keep[c] = kept;
            int n = 0;
            u64 kw = kept;
            while (kw) {
                int b = __ffsll((long long)kw) - 1;
                kw &= kw - 1ULL;
                klist[n++] = c * 64 + b;
            }
            kcnt_sh = n;
        }
        __syncthreads();                             // S1: kept list visible
        // (C) OR kept rows into remv for future chunks
        if (t > c && t < Mw) {
            int n = kcnt_sh;
            u64 acc = remv[t];
            for (int i = 0; i < n; i++)
                acc |= g_mask[(size_t)klist[i] * NW + t];
            remv[t] = acc;
        }
        __syncthreads();                             // S2: remv + prefetch visible
    }
}

// ---------------- 6) write output: sorted boxes[:,1:5] * keep ----------------
__global__ void k_out(float4* __restrict__ out) {
    int i = blockIdx.x * blockDim.x + threadIdx.x;
    if (i >= NBOX) return;
    u64 kw = g_keep[i >> 6];
    float4 v = ((kw >> (i & 63)) & 1ULL) ? g_seph[i] : make_float4(0.f, 0.f, 0.f, 0.f);
    out[i] = v;
}

extern "C" void kernel_launch(void* const* d_in, const int* in_sizes, int n_in,
                              void* d_out, int out_size) {
    const float* in = (const float*)d_in[0];
    float4* out = (float4*)d_out;
    (void)in_sizes; (void)n_in; (void)out_size;

    k_prep   <<<64, 256>>>(in);
    k_rank   <<<dim3(64, 4), 256>>>();
    k_scatter<<<64, 256>>>(in);
    k_mask   <<<dim3(256, 256), 64>>>();
    k_scan   <<<1, 256>>>();
    k_out    <<<64, 256>>>(out);
}

// round 4
// speedup vs baseline: 1.9642x; 1.1399x over previous
#include <cuda_runtime.h>

#define NBOX 16384
#define NW   256            // 64-bit words per mask row
#define NBKT 16384          // conf buckets for counting sort
#define CONF_THRESH 0.5f
#define PIOU_THRESH 0.5f

typedef unsigned long long u64;

// ---------------- device scratch (static; no allocation) ----------------
__device__ float4 g_seph[NBOX];                    // sorted [start,end,peak,height]
__device__ float  g_conf[NBOX];                    // dense confidence (unsorted)
__device__ int    g_hist[NBKT];                    // bucket histogram
__device__ int    g_off[NBKT];                     // #elements in buckets > b
__device__ int    g_cnt[NBKT];                     // scatter cursors
__device__ int    g_blist[NBOX];                   // bucket-grouped original indices
__device__ int    g_M;                             // count(conf > 0.5) == valid prefix len
__device__ u64    g_mask[(size_t)NBOX * NW];       // 32MB suppression bitmask
__device__ u64    g_keep[NW];                      // final keep bits (sorted order)

__device__ __forceinline__ int bucket_of(float c) {
    int b = (int)(c * 16384.0f);                   // exact pow2 mul; monotone
    return b > 16383 ? 16383 : b;
}

// ---------------- 1) gather conf, zero accumulators ----------------
__global__ void k_prep(const float* __restrict__ in) {
    int i = blockIdx.x * blockDim.x + threadIdx.x;
    if (i < NBOX) {
        g_conf[i] = in[i * 5 + 0];
        g_hist[i] = 0;
        g_cnt[i]  = 0;
    }
    if (i == 0) g_M = 0;
}

// ---------------- 2a) bucket histogram ----------------
__global__ void k_hist() {
    int i = blockIdx.x * blockDim.x + threadIdx.x;
    if (i < NBOX) atomicAdd(&g_hist[bucket_of(g_conf[i])], 1);
}

// ---------------- 2b) suffix sums: off[b] = #elements with bucket > b ----------
__global__ void k_suffix() {                       // 1 block, 1024 threads
    __shared__ int part[1024];
    int t = threadIdx.x;
    int base = t * 16;
    int v[16]; int s = 0;
#pragma unroll
    for (int k = 0; k < 16; k++) { v[k] = g_hist[base + k]; s += v[k]; }
    part[t] = s;
    __syncthreads();
    for (int off = 1; off < 1024; off <<= 1) {     // inclusive suffix scan of partials
        int x = (t + off < 1024) ? part[t + off] : 0;
        __syncthreads();
        part[t] += x;
        __syncthreads();
    }
    int above = part[t] - s;                       // sum of buckets >= (t+1)*16
    int o[16];
    o[15] = above;
#pragma unroll
    for (int k = 14; k >= 0; k--) o[k] = o[k + 1] + v[k + 1];
#pragma unroll
    for (int k = 0; k < 16; k++) g_off[base + k] = o[k];
}

// ---------------- 2c) scatter indices into bucket segments ----------------
__global__ void k_bscatter() {
    int i = blockIdx.x * blockDim.x + threadIdx.x;
    if (i >= NBOX) return;
    int b = bucket_of(g_conf[i]);
    int pos = g_off[b] + atomicAdd(&g_cnt[b], 1);
    g_blist[pos] = i;
}

// ---------------- 3) exact rank within bucket + scatter boxes ----------------
__global__ void k_rankscatter(const float* __restrict__ in) {
    int i = blockIdx.x * blockDim.x + threadIdx.x;
    if (i >= NBOX) return;
    float ci = g_conf[i];
    int b    = bucket_of(ci);
    int base = g_off[b], len = g_hist[b];
    int cnt = 0;
    for (int p = base; p < base + len; p++) {
        int j = g_blist[p];
        float cj = g_conf[j];
        cnt += (cj > ci) || (cj == ci && j < i);   // stable: (conf desc, idx asc)
    }
    int r = base + cnt;
    const float* row = in + (size_t)i * 5;
    g_seph[r] = make_float4(row[1], row[2], row[3], row[4]);
    if (ci > CONF_THRESH) atomicAdd(&g_M, 1);
}

// ---------------- 4) pairwise peak-IoU bitmask, upper-triangular blocks only ----
// grid = (256, 256), block = 64. Scan only reads words t >= row-chunk, so
// blocks with bx < by are dead. j<M / j!=r hoisted out of the inner loop.
__global__ void k_mask() {
    __shared__ float4 cols[64];
    if (blockIdx.x < blockIdx.y) return;           // triangular: halves the work
    int M = g_M;
    if ((int)(blockIdx.y * 64) >= M) return;
    int j0 = blockIdx.x * 64;
    if (j0 >= M) return;
    int r = blockIdx.y * 64 + threadIdx.x;
    cols[threadIdx.x] = g_seph[j0 + threadIdx.x];
    __syncthreads();
    if (r >= M) return;
    float4 a = g_seph[r];
    float area1 = __fmul_rn(__fsub_rn(a.y, a.x), a.w);
    u64 w = 0;
#pragma unroll 4
    for (int k = 0; k < 64; k++) {
        float4 b = cols[k];
        float is = fmaxf(a.x, b.x);
        float ie = fminf(a.y, b.y);
        float il = __fsub_rn(ie, is);
        bool sup = false;
        if (il > 0.0f) {                           // piou>0 requires overlap
            float inter_h    = fminf(a.w, b.w);
            float inter_area = __fmul_rn(il, inter_h);
            float area2      = __fmul_rn(__fsub_rn(b.y, b.x), b.w);
            float union_area = __fsub_rn(__fadd_rn(area1, area2), inter_area);
            float iou        = __fdiv_rn(inter_area, union_area);
            float pd         = fabsf(__fsub_rn(a.z, b.z));
            float us         = fminf(a.x, b.x);
            float ue         = fmaxf(a.y, b.y);
            float ud         = fabsf(__fsub_rn(ue, us));
            float val        = __fsub_rn(iou, __fdiv_rn(pd, ud));
            sup = (val > PIOU_THRESH);
        }
        w |= ((u64)sup) << k;
    }
    int lim = M - j0;                              // mask invalid cols once
    if (lim < 64) w &= (1ULL << lim) - 1ULL;
    if (r >= j0 && r < j0 + 64) w &= ~(1ULL << (r - j0));   // self never suppresses
    g_mask[(size_t)r * NW + blockIdx.x] = w;
}

// ---------------- 5) greedy scan, chunked 64-at-a-time, register chain ----------
__global__ void __launch_bounds__(256, 1) k_scan() {
    __shared__ u64 remv[NW];
    __shared__ u64 diag[2][64];
    __shared__ u64 kept_sh;
    __shared__ int klist[64];
    __shared__ int kcnt_sh;
    int t = threadIdx.x;
    remv[t] = 0ULL;
    int M  = g_M;
    int Mw = (M + 63) >> 6;
    if (t >= Mw) g_keep[t] = 0ULL;                 // zero unused keep words
    if (t < 64) {                                  // load chunk 0 diag
        diag[0][t] = (t < M) ? g_mask[(size_t)t * NW + 0] : 0ULL;
    }
    __syncthreads();

    for (int c = 0; c < Mw; c++) {
        int buf = c & 1;
        // (A) prefetch next chunk's diagonal block
        if (t >= 64 && t < 128 && (c + 1) < Mw) {
            int r = (c + 1) * 64 + (t - 64);
            diag[buf ^ 1][t - 64] = (r < M) ? g_mask[(size_t)r * NW + (c + 1)] : 0ULL;
        }
        // (B) serial chain in registers
        if (t == 0) {
            u64 d[64];
#pragma unroll
            for (int b = 0; b < 64; b++) d[b] = diag[buf][b];
            u64 rm   = remv[c];
            u64 kept = 0ULL;
#pragma unroll
            for (int b = 0; b < 64; b++) {
                u64 m = ((rm >> b) & 1ULL) - 1ULL;   // ~0 keep, 0 removed
                kept |= (1ULL << b) & m;
                rm   |= d[b] & m;
            }
            int lim = M - (c << 6);
            u64 vmask = (lim >= 64) ? ~0ULL : ((1ULL << lim) - 1ULL);
            kept &= vmask;
            kept_sh   = kept;
            g_keep[c] = kept;
            int n = 0;
            u64 kw = kept;
            while (kw) {
                int b = __ffsll((long long)kw) - 1;
                kw &= kw - 1ULL;
                klist[n++] = c * 64 + b;
            }
            kcnt_sh = n;
        }
        __syncthreads();                             // S1: kept list visible
        // (C) OR kept rows into remv for future chunks
        if (t > c && t < Mw) {
            int n = kcnt_sh;
            u64 acc = remv[t];
            for (int i = 0; i < n; i++)
                acc |= g_mask[(size_t)klist[i] * NW + t];
            remv[t] = acc;
        }
        __syncthreads();                             // S2: remv + prefetch visible
    }
}

// ---------------- 6) write output: sorted boxes[:,1:5] * keep ----------------
__global__ void k_out(float4* __restrict__ out) {
    int i = blockIdx.x * blockDim.x + threadIdx.x;
    if (i >= NBOX) return;
    u64 kw = g_keep[i >> 6];
    float4 v = ((kw >> (i & 63)) & 1ULL) ? g_seph[i] : make_float4(0.f, 0.f, 0.f, 0.f);
    out[i] = v;
}

extern "C" void kernel_launch(void* const* d_in, const int* in_sizes, int n_in,
                              void* d_out, int out_size) {
    const float* in = (const float*)d_in[0];
    float4* out = (float4*)d_out;
    (void)in_sizes; (void)n_in; (void)out_size;

    k_prep       <<<64, 256>>>(in);
    k_hist       <<<64, 256>>>();
    k_suffix     <<<1, 1024>>>();
    k_bscatter   <<<64, 256>>>();
    k_rankscatter<<<64, 256>>>(in);
    k_mask       <<<dim3(256, 256), 64>>>();
    k_scan       <<<1, 256>>>();
    k_out        <<<64, 256>>>(out);
}

// round 5
// speedup vs baseline: 3.1951x; 1.6267x over previous
#include <cuda_runtime.h>

#define NBOX 16384
#define NW   256            // 64-bit words per mask row
#define NBKT 16384          // conf buckets for counting sort
#define CONF_THRESH 0.5f
#define PIOU_THRESH 0.5f

typedef unsigned long long u64;

// ---------------- device scratch (static; no allocation) ----------------
__device__ float4 g_seph[NBOX];                    // sorted [start,end,peak,height]
__device__ float  g_conf[NBOX];                    // dense confidence (unsorted)
__device__ int    g_hist[NBKT];                    // bucket histogram
__device__ int    g_off[NBKT];                     // #elements in buckets > b
__device__ int    g_cnt[NBKT];                     // scatter cursors
__device__ int    g_blist[NBOX];                   // bucket-grouped original indices
__device__ int    g_M;                             // count(conf > 0.5) == valid prefix len
__device__ u64    g_mask[(size_t)NBOX * NW];       // 32MB suppression bitmask
__device__ u64    g_keep[NW];                      // final keep bits (sorted order)

__device__ __forceinline__ int bucket_of(float c) {
    int b = (int)(c * 16384.0f);                   // exact pow2 mul; monotone
    return b > 16383 ? 16383 : b;
}

// ---------------- 1) gather conf, zero accumulators ----------------
__global__ void k_prep(const float* __restrict__ in) {
    int i = blockIdx.x * blockDim.x + threadIdx.x;
    if (i < NBOX) {
        g_conf[i] = in[i * 5 + 0];
        g_hist[i] = 0;
        g_cnt[i]  = 0;
    }
    if (i == 0) g_M = 0;
}

// ---------------- 2a) bucket histogram ----------------
__global__ void k_hist() {
    int i = blockIdx.x * blockDim.x + threadIdx.x;
    if (i < NBOX) atomicAdd(&g_hist[bucket_of(g_conf[i])], 1);
}

// ---------------- 2b) suffix sums: off[b] = #elements with bucket > b ----------
__global__ void k_suffix() {                       // 1 block, 1024 threads
    __shared__ int part[1024];
    int t = threadIdx.x;
    int base = t * 16;
    int v[16]; int s = 0;
#pragma unroll
    for (int k = 0; k < 16; k++) { v[k] = g_hist[base + k]; s += v[k]; }
    part[t] = s;
    __syncthreads();
    for (int off = 1; off < 1024; off <<= 1) {     // inclusive suffix scan of partials
        int x = (t + off < 1024) ? part[t + off] : 0;
        __syncthreads();
        part[t] += x;
        __syncthreads();
    }
    int above = part[t] - s;                       // sum of buckets >= (t+1)*16
    int o[16];
    o[15] = above;
#pragma unroll
    for (int k = 14; k >= 0; k--) o[k] = o[k + 1] + v[k + 1];
#pragma unroll
    for (int k = 0; k < 16; k++) g_off[base + k] = o[k];
}

// ---------------- 2c) scatter indices into bucket segments ----------------
__global__ void k_bscatter() {
    int i = blockIdx.x * blockDim.x + threadIdx.x;
    if (i >= NBOX) return;
    int b = bucket_of(g_conf[i]);
    int pos = g_off[b] + atomicAdd(&g_cnt[b], 1);
    g_blist[pos] = i;
}

// ---------------- 3) exact rank within bucket + scatter boxes ----------------
__global__ void k_rankscatter(const float* __restrict__ in) {
    int i = blockIdx.x * blockDim.x + threadIdx.x;
    if (i >= NBOX) return;
    float ci = g_conf[i];
    int b    = bucket_of(ci);
    int base = g_off[b], len = g_hist[b];
    int cnt = 0;
    for (int p = base; p < base + len; p++) {
        int j = g_blist[p];
        float cj = g_conf[j];
        cnt += (cj > ci) || (cj == ci && j < i);   // stable: (conf desc, idx asc)
    }
    int r = base + cnt;
    const float* row = in + (size_t)i * 5;
    g_seph[r] = make_float4(row[1], row[2], row[3], row[4]);
    if (ci > CONF_THRESH) atomicAdd(&g_M, 1);
}

// ---------------- 4) pairwise peak-IoU bitmask, upper-triangular blocks only ----
__global__ void k_mask() {
    __shared__ float4 cols[64];
    if (blockIdx.x < blockIdx.y) return;           // triangular: halves the work
    int M = g_M;
    if ((int)(blockIdx.y * 64) >= M) return;
    int j0 = blockIdx.x * 64;
    if (j0 >= M) return;
    int r = blockIdx.y * 64 + threadIdx.x;
    cols[threadIdx.x] = g_seph[j0 + threadIdx.x];
    __syncthreads();
    if (r >= M) return;
    float4 a = g_seph[r];
    float area1 = __fmul_rn(__fsub_rn(a.y, a.x), a.w);
    u64 w = 0;
#pragma unroll 4
    for (int k = 0; k < 64; k++) {
        float4 b = cols[k];
        float is = fmaxf(a.x, b.x);
        float ie = fminf(a.y, b.y);
        float il = __fsub_rn(ie, is);
        bool sup = false;
        if (il > 0.0f) {                           // piou>0 requires overlap
            float inter_h    = fminf(a.w, b.w);
            float inter_area = __fmul_rn(il, inter_h);
            float area2      = __fmul_rn(__fsub_rn(b.y, b.x), b.w);
            float union_area = __fsub_rn(__fadd_rn(area1, area2), inter_area);
            float iou        = __fdiv_rn(inter_area, union_area);
            float pd         = fabsf(__fsub_rn(a.z, b.z));
            float us         = fminf(a.x, b.x);
            float ue         = fmaxf(a.y, b.y);
            float ud         = fabsf(__fsub_rn(ue, us));
            float val        = __fsub_rn(iou, __fdiv_rn(pd, ud));
            sup = (val > PIOU_THRESH);
        }
        w |= ((u64)sup) << k;
    }
    int lim = M - j0;                              // mask invalid cols once
    if (lim < 64) w &= (1ULL << lim) - 1ULL;
    if (r >= j0 && r < j0 + 64) w &= ~(1ULL << (r - j0));   // self never suppresses
    g_mask[(size_t)r * NW + blockIdx.x] = w;
}

// ---------------- 5) greedy scan: zero-skip chain + MLP-batched OR gather ------
// Single CTA, 256 threads, Mw chunks of 64 rows. Per chunk:
//   (A) threads 64..127 prefetch next chunk's diag (double buffered)
//   (B) thread 0: zero-skip greedy over avail bits (iterations = kept count),
//       builds klist inline, pads to multiple of 8 with klist[0] (OR idempotent)
//   S1; (C) threads t in (c, Mw): 8-wide unrolled OR of kept rows' word t; S2.
__global__ void __launch_bounds__(256, 1) k_scan() {
    __shared__ u64 remv[NW];
    __shared__ u64 diag[2][64];
    __shared__ int klist[72];
    __shared__ int n8_sh;
    int t = threadIdx.x;
    remv[t] = 0ULL;
    int M  = g_M;
    int Mw = (M + 63) >> 6;
    if (t >= Mw) g_keep[t] = 0ULL;                 // zero unused keep words
    if (t < 64) {                                  // load chunk 0 diag
        diag[0][t] = (t < M) ? g_mask[(size_t)t * NW + 0] : 0ULL;
    }
    __syncthreads();

    for (int c = 0; c < Mw; c++) {
        int buf = c & 1;
        // (A) prefetch next chunk's diagonal block
        if (t >= 64 && t < 128 && (c + 1) < Mw) {
            int r = (c + 1) * 64 + (t - 64);
            diag[buf ^ 1][t - 64] = (r < M) ? g_mask[(size_t)r * NW + (c + 1)] : 0ULL;
        }
        // (B) zero-skip greedy chain: only visit kept bits
        if (t == 0) {
            int lim = M - (c << 6);
            u64 vmask = (lim >= 64) ? ~0ULL : ((1ULL << lim) - 1ULL);
            u64 avail = vmask & ~remv[c];
            u64 kept  = 0ULL;
            int n = 0;
            int cbase = c << 6;
            while (avail) {
                int b = __ffsll((long long)avail) - 1;
                u64 bit = 1ULL << b;
                kept |= bit;
                klist[n++] = cbase + b;
                avail &= ~(diag[buf][b] | bit);    // drop b + everything it suppresses
            }
            g_keep[c] = kept;
            int n8 = (n + 7) & ~7;                 // pad with klist[0] (idempotent OR)
            for (int p = n; p < n8; p++) klist[p] = klist[0];
            n8_sh = n8;
        }
        __syncthreads();                           // S1: klist/n8 visible
        // (C) OR kept rows into remv for future chunks, 8 loads in flight
        if (t > c && t < Mw) {
            int n8 = n8_sh;
            u64 acc = remv[t];
            for (int i = 0; i < n8; i += 8) {
                u64 v0 = g_mask[(size_t)klist[i + 0] * NW + t];
                u64 v1 = g_mask[(size_t)klist[i + 1] * NW + t];
                u64 v2 = g_mask[(size_t)klist[i + 2] * NW + t];
                u64 v3 = g_mask[(size_t)klist[i + 3] * NW + t];
                u64 v4 = g_mask[(size_t)klist[i + 4] * NW + t];
                u64 v5 = g_mask[(size_t)klist[i + 5] * NW + t];
                u64 v6 = g_mask[(size_t)klist[i + 6] * NW + t];
                u64 v7 = g_mask[(size_t)klist[i + 7] * NW + t];
                acc |= ((v0 | v1) | (v2 | v3)) | ((v4 | v5) | (v6 | v7));
            }
            remv[t] = acc;
        }
        __syncthreads();                           // S2: remv + prefetch visible
    }
}

// ---------------- 6) write output: sorted boxes[:,1:5] * keep ----------------
__global__ void k_out(float4* __restrict__ out) {
    int i = blockIdx.x * blockDim.x + threadIdx.x;
    if (i >= NBOX) return;
    u64 kw = g_keep[i >> 6];
    float4 v = ((kw >> (i & 63)) & 1ULL) ? g_seph[i] : make_float4(0.f, 0.f, 0.f, 0.f);
    out[i] = v;
}

extern "C" void kernel_launch(void* const* d_in, const int* in_sizes, int n_in,
                              void* d_out, int out_size) {
    const float* in = (const float*)d_in[0];
    float4* out = (float4*)d_out;
    (void)in_sizes; (void)n_in; (void)out_size;

    k_prep       <<<64, 256>>>(in);
    k_hist       <<<64, 256>>>();
    k_suffix     <<<1, 1024>>>();
    k_bscatter   <<<64, 256>>>();
    k_rankscatter<<<64, 256>>>(in);
    k_mask       <<<dim3(256, 256), 64>>>();
    k_scan       <<<1, 256>>>();
    k_out        <<<64, 256>>>(out);
}